// round 1
// baseline (speedup 1.0000x reference)
#include <cuda_runtime.h>
#include <cuda_bf16.h>
#include <math_constants.h>

// Problem: B=32, N=4096, D=1024.
// out[b,n] = softmax_n( x[b,n,:] . w_x )   (hidden/bias terms are constant
// over n and cancel inside softmax).

#define B_SZ 32
#define N_SZ 4096
#define D_SZ 1024

// Scratch for logits (no cudaMalloc allowed).
__device__ float g_logits[B_SZ * N_SZ];

// ---------------------------------------------------------------------------
// Kernel 1: logits[row] = dot(x[row, :], w_x).  One warp per row.
// Block = 256 threads = 8 warps = 8 rows. Grid = (B*N)/8 = 16384 blocks.
// ---------------------------------------------------------------------------
__global__ __launch_bounds__(256) void dot_kernel(
    const float* __restrict__ x,
    const float* __restrict__ w,
    float* __restrict__ logits)
{
    __shared__ float sw[D_SZ];
    const int tid = threadIdx.x;

    // Stage w_x in shared (4 KB), coalesced.
    #pragma unroll
    for (int i = tid; i < D_SZ; i += 256) sw[i] = w[i];
    __syncthreads();

    const int warp = tid >> 5;
    const int lane = tid & 31;
    const long long row = (long long)blockIdx.x * 8 + warp;  // < B*N always

    const float4* __restrict__ xr =
        reinterpret_cast<const float4*>(x + row * (long long)D_SZ);
    const float4* __restrict__ wr = reinterpret_cast<const float4*>(sw);

    float acc = 0.0f;
    #pragma unroll
    for (int k = 0; k < 8; ++k) {
        // lanes 0..31 hit consecutive float4s -> 512B fully coalesced, MLP=8
        const float4 xv = xr[k * 32 + lane];
        const float4 wv = wr[k * 32 + lane];
        acc = fmaf(xv.x, wv.x, acc);
        acc = fmaf(xv.y, wv.y, acc);
        acc = fmaf(xv.z, wv.z, acc);
        acc = fmaf(xv.w, wv.w, acc);
    }

    #pragma unroll
    for (int off = 16; off > 0; off >>= 1)
        acc += __shfl_xor_sync(0xFFFFFFFFu, acc, off);

    if (lane == 0) logits[row] = acc;
}

// ---------------------------------------------------------------------------
// Kernel 2: per-batch softmax over N=4096. One block (1024 thr) per batch.
// Each thread owns 4 elements.
// ---------------------------------------------------------------------------
__global__ __launch_bounds__(1024) void softmax_kernel(
    const float* __restrict__ logits,
    float* __restrict__ out)
{
    const int b   = blockIdx.x;
    const int tid = threadIdx.x;
    const float* __restrict__ l = logits + b * N_SZ;
    float* __restrict__ o       = out    + b * N_SZ;

    __shared__ float red[32];

    // Load 4 values (vectorized).
    float4 v = reinterpret_cast<const float4*>(l)[tid];

    // ---- block max ----
    float m = fmaxf(fmaxf(v.x, v.y), fmaxf(v.z, v.w));
    #pragma unroll
    for (int off = 16; off > 0; off >>= 1)
        m = fmaxf(m, __shfl_xor_sync(0xFFFFFFFFu, m, off));
    if ((tid & 31) == 0) red[tid >> 5] = m;
    __syncthreads();
    if (tid < 32) {
        float t = red[tid];
        #pragma unroll
        for (int off = 16; off > 0; off >>= 1)
            t = fmaxf(t, __shfl_xor_sync(0xFFFFFFFFu, t, off));
        red[tid] = t;
    }
    __syncthreads();
    const float gmax = red[0];
    __syncthreads();

    // ---- exp + block sum ----
    v.x = __expf(v.x - gmax);
    v.y = __expf(v.y - gmax);
    v.z = __expf(v.z - gmax);
    v.w = __expf(v.w - gmax);
    float s = v.x + v.y + v.z + v.w;
    #pragma unroll
    for (int off = 16; off > 0; off >>= 1)
        s += __shfl_xor_sync(0xFFFFFFFFu, s, off);
    if ((tid & 31) == 0) red[tid >> 5] = s;
    __syncthreads();
    if (tid < 32) {
        float t = red[tid];
        #pragma unroll
        for (int off = 16; off > 0; off >>= 1)
            t += __shfl_xor_sync(0xFFFFFFFFu, t, off);
        red[tid] = t;
    }
    __syncthreads();
    const float inv = 1.0f / red[0];

    v.x *= inv; v.y *= inv; v.z *= inv; v.w *= inv;
    reinterpret_cast<float4*>(o)[tid] = v;
}

// ---------------------------------------------------------------------------
// Launch. Inputs (metadata order): fixed_inputs [B,N,D], hidden [B,D_STATE],
// w_x [D], w_h [D_STATE], b [] — hidden/w_h/b are softmax-invariant, unused.
// ---------------------------------------------------------------------------
extern "C" void kernel_launch(void* const* d_in, const int* in_sizes, int n_in,
                              void* d_out, int out_size)
{
    const float* x   = (const float*)d_in[0];
    const float* w_x = (const float*)d_in[2];
    float* out = (float*)d_out;

    float* logits;
    cudaGetSymbolAddress((void**)&logits, g_logits);

    dot_kernel<<<(B_SZ * N_SZ) / 8, 256>>>(x, w_x, logits);
    softmax_kernel<<<B_SZ, 1024>>>(logits, out);
}